// round 5
// baseline (speedup 1.0000x reference)
#include <cuda_runtime.h>

// Elementwise affine: y = x * 2 + 5 over 8192*8192 fp32.
// Blackwell 256-bit vector memory ops: each thread does two
// ld.global.cs.v8.f32 (2x 32B = 64B/thread, same traffic as ILP=4 float4)
// but in half the LSU issue slots / L1tex queue entries.
// 8388608 float8 total; 256 thr/block * 2 float8/thr -> 16384 blocks.

__device__ __forceinline__ void ldcs_v8(const float* __restrict__ p, float* r) {
    asm volatile("ld.global.cs.v8.f32 {%0,%1,%2,%3,%4,%5,%6,%7}, [%8];"
                 : "=f"(r[0]), "=f"(r[1]), "=f"(r[2]), "=f"(r[3]),
                   "=f"(r[4]), "=f"(r[5]), "=f"(r[6]), "=f"(r[7])
                 : "l"(p));
}

__device__ __forceinline__ void stcs_v8(float* __restrict__ p, const float* r) {
    asm volatile("st.global.cs.v8.f32 [%0], {%1,%2,%3,%4,%5,%6,%7,%8};"
                 :: "l"(p),
                    "f"(r[0]), "f"(r[1]), "f"(r[2]), "f"(r[3]),
                    "f"(r[4]), "f"(r[5]), "f"(r[6]), "f"(r[7])
                 : "memory");
}

__global__ void __launch_bounds__(256) affine_kernel(const float* __restrict__ x,
                                                     float* __restrict__ y) {
    // each "slot" is 8 floats (32 bytes)
    unsigned int slot = blockIdx.x * 512u + threadIdx.x;   // slot index, 2 per thread
    unsigned long long off0 = (unsigned long long)slot * 8ull;
    unsigned long long off1 = (unsigned long long)(slot + 256u) * 8ull;

    float v0[8], v1[8];
    ldcs_v8(x + off0, v0);
    ldcs_v8(x + off1, v1);

    float r0[8], r1[8];
#pragma unroll
    for (int k = 0; k < 8; k++) r0[k] = fmaf(v0[k], 2.0f, 5.0f);
#pragma unroll
    for (int k = 0; k < 8; k++) r1[k] = fmaf(v1[k], 2.0f, 5.0f);

    stcs_v8(y + off0, r0);
    stcs_v8(y + off1, r1);
}

extern "C" void kernel_launch(void* const* d_in, const int* in_sizes, int n_in,
                              void* d_out, int out_size) {
    const float* x = (const float*)d_in[0];
    float* y = (float*)d_out;
    int n = in_sizes[0];             // 67108864 floats
    int n8 = n / 8;                  // 8388608 float8 slots
    int blocks = n8 / 512;           // 16384
    affine_kernel<<<blocks, 256>>>(x, y);
}

// round 6
// speedup vs baseline: 1.0059x; 1.0059x over previous
#include <cuda_runtime.h>

// Elementwise affine: y = x * 2 + 5 over 8192*8192 fp32.
// Final configuration (measured Pareto optimum across ILP/vector-width sweep):
// ILP=4 x 128-bit streaming loads/stores per thread, 26 regs, occ ~77%.
// DRAM-controller-bound at ~6.5 TB/s (82% of spec) on the mixed r/w stream;
// ILP=2/8 and 256-bit variants all measured equal or worse.
// 16777216 float4 total; 256 thr/block * 4 float4/thr -> 16384 blocks.

__global__ void __launch_bounds__(256) affine_kernel(const float4* __restrict__ x,
                                                     float4* __restrict__ y) {
    unsigned int base = blockIdx.x * 1024u + threadIdx.x;

    float4 v0 = __ldcs(&x[base]);
    float4 v1 = __ldcs(&x[base + 256u]);
    float4 v2 = __ldcs(&x[base + 512u]);
    float4 v3 = __ldcs(&x[base + 768u]);

    float4 r0, r1, r2, r3;
    r0.x = fmaf(v0.x, 2.0f, 5.0f); r0.y = fmaf(v0.y, 2.0f, 5.0f);
    r0.z = fmaf(v0.z, 2.0f, 5.0f); r0.w = fmaf(v0.w, 2.0f, 5.0f);
    r1.x = fmaf(v1.x, 2.0f, 5.0f); r1.y = fmaf(v1.y, 2.0f, 5.0f);
    r1.z = fmaf(v1.z, 2.0f, 5.0f); r1.w = fmaf(v1.w, 2.0f, 5.0f);
    r2.x = fmaf(v2.x, 2.0f, 5.0f); r2.y = fmaf(v2.y, 2.0f, 5.0f);
    r2.z = fmaf(v2.z, 2.0f, 5.0f); r2.w = fmaf(v2.w, 2.0f, 5.0f);
    r3.x = fmaf(v3.x, 2.0f, 5.0f); r3.y = fmaf(v3.y, 2.0f, 5.0f);
    r3.z = fmaf(v3.z, 2.0f, 5.0f); r3.w = fmaf(v3.w, 2.0f, 5.0f);

    __stcs(&y[base],         r0);
    __stcs(&y[base + 256u],  r1);
    __stcs(&y[base + 512u],  r2);
    __stcs(&y[base + 768u],  r3);
}

extern "C" void kernel_launch(void* const* d_in, const int* in_sizes, int n_in,
                              void* d_out, int out_size) {
    const float4* x = (const float4*)d_in[0];
    float4* y = (float4*)d_out;
    int n = in_sizes[0];            // 67108864
    int n4 = n / 4;                 // 16777216
    int blocks = n4 / 1024;         // 16384
    affine_kernel<<<blocks, 256>>>(x, y);
}